// round 14
// baseline (speedup 1.0000x reference)
#include <cuda_runtime.h>
#include <cuda_bf16.h>
#include <math.h>

// Problem constants
#define BB 2
#define NN 2048
#define DM 256     // d_model = H*DH
#define HH 8
#define DHD 32
#define KS 40      // attn smem row stride (bf16): 80B -> conflict-free ldmatrix
#define GS 72      // gemm smem row stride (bf16): 144B -> conflict-free ldmatrix

// ---------------------------------------------------------------------------
// Scratch (device globals: no allocations allowed)
// ---------------------------------------------------------------------------
__device__ __nv_bfloat16 g_xh[BB * NN * DM];          // x split hi
__device__ __nv_bfloat16 g_xl[BB * NN * DM];          // x split lo
__device__ __nv_bfloat16 g_wh[4 * DM * DM];           // Wq,Wk,Wv,Wo split hi
__device__ __nv_bfloat16 g_wl[4 * DM * DM];
__device__ __nv_bfloat16 g_ph[3 * BB * NN * DM];      // Q(scaled),K,V split hi
__device__ __nv_bfloat16 g_pl[3 * BB * NN * DM];
__device__ __nv_bfloat16 g_ah[BB * NN * DM];          // attn out split hi
__device__ __nv_bfloat16 g_al[BB * NN * DM];
__device__ unsigned      g_adjb[BB * NN * (NN / 32)]; // adjacency bitmask

// ---------------------------------------------------------------------------
// Helpers
// ---------------------------------------------------------------------------
__device__ __forceinline__ void mma16816(float d[4], const unsigned a[4],
                                         unsigned b0, unsigned b1)
{
    asm volatile(
        "mma.sync.aligned.m16n8k16.row.col.f32.bf16.bf16.f32 "
        "{%0,%1,%2,%3},{%4,%5,%6,%7},{%8,%9},{%0,%1,%2,%3};\n"
        : "+f"(d[0]), "+f"(d[1]), "+f"(d[2]), "+f"(d[3])
        : "r"(a[0]), "r"(a[1]), "r"(a[2]), "r"(a[3]), "r"(b0), "r"(b1));
}

__device__ __forceinline__ void ldsm4(unsigned &r0, unsigned &r1,
                                      unsigned &r2, unsigned &r3, unsigned addr)
{
    asm volatile("ldmatrix.sync.aligned.m8n8.x4.shared.b16 {%0,%1,%2,%3}, [%4];\n"
        : "=r"(r0), "=r"(r1), "=r"(r2), "=r"(r3) : "r"(addr));
}

__device__ __forceinline__ void ldsm4t(unsigned &r0, unsigned &r1,
                                       unsigned &r2, unsigned &r3, unsigned addr)
{
    asm volatile("ldmatrix.sync.aligned.m8n8.x4.trans.shared.b16 {%0,%1,%2,%3}, [%4];\n"
        : "=r"(r0), "=r"(r1), "=r"(r2), "=r"(r3) : "r"(addr));
}

// fast 2^x
__device__ __forceinline__ float ex2(float x)
{
    float y;
    asm("ex2.approx.ftz.f32 %0, %1;" : "=f"(y) : "f"(x));
    return y;
}

// split two fp32 into (hi, lo) bf16x2 packed registers (x -> low half)
__device__ __forceinline__ void split2(float x, float y, unsigned &hi, unsigned &lo)
{
    __nv_bfloat16 hx = __float2bfloat16(x);
    __nv_bfloat16 hy = __float2bfloat16(y);
    float rx = x - __bfloat162float(hx);
    float ry = y - __bfloat162float(hy);
    __nv_bfloat162 hv = __halves2bfloat162(hx, hy);
    __nv_bfloat162 lv = __halves2bfloat162(__float2bfloat16(rx), __float2bfloat16(ry));
    hi = *reinterpret_cast<unsigned*>(&hv);
    lo = *reinterpret_cast<unsigned*>(&lv);
}

__device__ __forceinline__ void split_store4(float4 v, __nv_bfloat16* hp, __nv_bfloat16* lp)
{
    unsigned h01, l01, h23, l23;
    split2(v.x, v.y, h01, l01);
    split2(v.z, v.w, h23, l23);
    *reinterpret_cast<unsigned*>(hp)     = h01;
    *reinterpret_cast<unsigned*>(hp + 2) = h23;
    *reinterpret_cast<unsigned*>(lp)     = l01;
    *reinterpret_cast<unsigned*>(lp + 2) = l23;
}

__device__ __forceinline__ void cp_async16(unsigned dst, const void* src)
{
    asm volatile("cp.async.cg.shared.global [%0], [%1], 16;\n" :: "r"(dst), "l"(src));
}

// ---------------------------------------------------------------------------
// Prep kernel: blocks [0,1024) split x, [1024,1280) split W
// (adjacency bitmask prep is folded into the QKV GEMM launch, z==3)
// ---------------------------------------------------------------------------
__global__ __launch_bounds__(256) void prep_kernel(
    const float* __restrict__ x,
    const float* __restrict__ wq, const float* __restrict__ wk,
    const float* __restrict__ wv, const float* __restrict__ wo)
{
    const int bid = blockIdx.x;
    if (bid < 1024) {
        int i = bid * 256 + threadIdx.x;               // 262144 float4
        float4 v = ((const float4*)x)[i];
        split_store4(v, g_xh + i * 4, g_xl + i * 4);
    } else {
        int i = (bid - 1024) * 256 + threadIdx.x;      // 65536 float4
        int seg = i >> 14;
        int off = i & 16383;
        const float* src = (seg == 0) ? wq : (seg == 1) ? wk : (seg == 2) ? wv : wo;
        float4 v = ((const float4*)src)[off];
        split_store4(v, g_wh + (size_t)seg * DM * DM + off * 4,
                        g_wl + (size_t)seg * DM * DM + off * 4);
    }
}

// ---------------------------------------------------------------------------
// bf16-split tensor-core GEMM: C[4096 x 256] = A @ W^T
// Block tile 64x64, 8 warps = 4 row-groups x 2 col-groups (warp: 16r x 32c).
// K=256 in 4 stages of 64, cp.async depth-2 pipeline, term-major MMAs.
// z < 3: gemm with weight segment z; z == 3 (adj != nullptr): adjacency bits.
// ---------------------------------------------------------------------------
#define GT_ELEM (64 * GS)                       // one 64-row buffer (bf16 elems)
#define GSTAGE_ELEM (4 * GT_ELEM)               // Ah, Al, Wh, Wl
#define GSTAGE_B (GSTAGE_ELEM * 2)

__global__ __launch_bounds__(256, 2) void gemm_split(
    const __nv_bfloat16* __restrict__ Ah, const __nv_bfloat16* __restrict__ Al,
    const __nv_bfloat16* __restrict__ Whb, const __nv_bfloat16* __restrict__ Wlb,
    __nv_bfloat16* __restrict__ Ohb, __nv_bfloat16* __restrict__ Olb,
    float* __restrict__ Of, const float* __restrict__ bias, float scale0,
    const float* __restrict__ adj)
{
    extern __shared__ __align__(16) __nv_bfloat16 sg[];

    const int t = threadIdx.x, w = t >> 5, lane = t & 31;
    const int z = blockIdx.z;

    // --- adjacency bitmask slice (runs concurrently with the QKV gemm) ---
    if (z == 3) {
        int cta  = blockIdx.y * gridDim.x + blockIdx.x;   // 0..255
        int slot = cta * 8 + w;                           // 0..2047
        #pragma unroll
        for (int i = 0; i < 4; ++i) {
            int gw = slot + 2048 * i;                     // 8192 warp-chunks
            size_t base = (size_t)gw * 1024;
            unsigned my = 0;
            #pragma unroll 8
            for (int k = 0; k < 32; ++k) {
                float v = adj[base + (size_t)k * 32 + lane];
                unsigned word = __ballot_sync(0xffffffffu, v != 0.0f);
                if (lane == k) my = word;
            }
            g_adjb[(size_t)gw * 32 + lane] = my;
        }
        return;
    }

    const int m0 = blockIdx.x * 64, n0 = blockIdx.y * 64;
    const __nv_bfloat16* srcs[4] = {
        Ah + (size_t)m0 * DM, Al + (size_t)m0 * DM,
        Whb + (size_t)z * DM * DM + (size_t)n0 * DM,
        Wlb + (size_t)z * DM * DM + (size_t)n0 * DM
    };

    const unsigned sb = (unsigned)__cvta_generic_to_shared(sg);

    float acc[4][4];
    #pragma unroll
    for (int i = 0; i < 4; ++i)
        #pragma unroll
        for (int j = 0; j < 4; ++j) acc[i][j] = 0.0f;

    // stage copy: 4 bufs x 64 rows x 8 chunks(16B) = 2048 chunks / 256 thr = 8
    auto issue_stage = [&](int s) {
        const int k0 = s * 64;
        const unsigned dstb = sb + (s & 1) * GSTAGE_B;
        #pragma unroll
        for (int i = 0; i < 8; ++i) {
            int idx = t + i * 256;
            int buf = idx >> 9;
            int rem = idx & 511;
            int row = rem >> 3, ch = rem & 7;
            const __nv_bfloat16* src = srcs[buf] + (size_t)row * DM + k0 + ch * 8;
            cp_async16(dstb + (buf * GT_ELEM + row * GS + ch * 8) * 2, src);
        }
    };

    issue_stage(0);
    asm volatile("cp.async.commit_group;\n");

    for (int s = 0; s < 4; ++s) {
        if (s + 1 < 4) {
            issue_stage(s + 1);
            asm volatile("cp.async.commit_group;\n");
            asm volatile("cp.async.wait_group 1;\n");
        } else {
            asm volatile("cp.async.wait_group 0;\n");
        }
        __syncthreads();

        const unsigned st  = sb + (s & 1) * GSTAGE_B;
        const unsigned SAH = st;
        const unsigned SAL = st + GT_ELEM * 2;
        const unsigned SWH = st + 2 * GT_ELEM * 2;
        const unsigned SWL = st + 3 * GT_ELEM * 2;

        #pragma unroll
        for (int ks = 0; ks < 4; ++ks) {
            unsigned ah[4], al[4];
            int arow = (w & 3) * 16 + (lane & 15);
            int acol = ks * 16 + ((lane & 16) ? 8 : 0);
            ldsm4(ah[0], ah[1], ah[2], ah[3], SAH + (arow * GS + acol) * 2);
            ldsm4(al[0], al[1], al[2], al[3], SAL + (arow * GS + acol) * 2);

            unsigned bh[2][4], bl[2][4];
            #pragma unroll
            for (int nt = 0; nt < 2; ++nt) {
                int brow = (w >> 2) * 32 + nt * 16 + (lane & 7) + ((lane & 16) ? 8 : 0);
                int bcol = ks * 16 + ((lane & 8) ? 8 : 0);
                ldsm4(bh[nt][0], bh[nt][1], bh[nt][2], bh[nt][3], SWH + (brow * GS + bcol) * 2);
                ldsm4(bl[nt][0], bl[nt][1], bl[nt][2], bl[nt][3], SWL + (brow * GS + bcol) * 2);
            }
            // term hh
            mma16816(acc[0], ah, bh[0][0], bh[0][1]);
            mma16816(acc[1], ah, bh[0][2], bh[0][3]);
            mma16816(acc[2], ah, bh[1][0], bh[1][1]);
            mma16816(acc[3], ah, bh[1][2], bh[1][3]);
            // term lh
            mma16816(acc[0], al, bh[0][0], bh[0][1]);
            mma16816(acc[1], al, bh[0][2], bh[0][3]);
            mma16816(acc[2], al, bh[1][0], bh[1][1]);
            mma16816(acc[3], al, bh[1][2], bh[1][3]);
            // term hl
            mma16816(acc[0], ah, bl[0][0], bl[0][1]);
            mma16816(acc[1], ah, bl[0][2], bl[0][3]);
            mma16816(acc[2], ah, bl[1][0], bl[1][1]);
            mma16816(acc[3], ah, bl[1][2], bl[1][3]);
        }
        __syncthreads();
    }

    const int r = lane >> 2, c2 = (lane & 3) * 2;
    const int row0 = m0 + (w & 3) * 16 + r;
    const int colb = n0 + (w >> 2) * 32;
    if (Of) {
        #pragma unroll
        for (int j = 0; j < 4; ++j) {
            int col = colb + 8 * j + c2;
            float b0v = bias[col], b1v = bias[col + 1];
            *(float2*)(Of + (size_t)row0 * DM + col) =
                make_float2(acc[j][0] + b0v, acc[j][1] + b1v);
            *(float2*)(Of + (size_t)(row0 + 8) * DM + col) =
                make_float2(acc[j][2] + b0v, acc[j][3] + b1v);
        }
    } else {
        const float sc = (z == 0) ? scale0 : 1.0f;
        __nv_bfloat16* Oh = Ohb + (size_t)z * BB * NN * DM;
        __nv_bfloat16* Ol = Olb + (size_t)z * BB * NN * DM;
        #pragma unroll
        for (int j = 0; j < 4; ++j) {
            int col = colb + 8 * j + c2;
            unsigned h0, l0, h1, l1;
            split2(acc[j][0] * sc, acc[j][1] * sc, h0, l0);
            split2(acc[j][2] * sc, acc[j][3] * sc, h1, l1);
            *(unsigned*)(Oh + (size_t)row0 * DM + col)       = h0;
            *(unsigned*)(Ol + (size_t)row0 * DM + col)       = l0;
            *(unsigned*)(Oh + (size_t)(row0 + 8) * DM + col) = h1;
            *(unsigned*)(Ol + (size_t)(row0 + 8) * DM + col) = l1;
        }
    }
}

// ---------------------------------------------------------------------------
// Fused masked attention, bf16-split MMA, cp.async double-buffered K/V,
// bitmask adjacency. Q pre-scaled by (1/sqrt(dh))*log2(e): p = 2^s.
// Warp-staggered halves: odd warps process half 1 first, anti-aligning the
// exp/pack phases across warps so the tensor pipe stays fed.
// ---------------------------------------------------------------------------
#define STAGE_B (4 * 128 * KS * 2)   // bytes per stage (Kh,Kl,Vh,Vl)
#define BUF_B   (128 * KS * 2)

__global__ __launch_bounds__(256, 2) void attn_mma(int dummy)
{
    extern __shared__ __align__(16) __nv_bfloat16 skv[];  // 2 stages

    const int t    = threadIdx.x;
    const int w    = t >> 5;
    const int lane = t & 31;
    const int r    = lane >> 2;
    const int c2   = (lane & 3) * 2;
    const int q0   = blockIdx.x * 128;
    const int h    = blockIdx.y;
    const int b    = blockIdx.z;

    const __nv_bfloat16* Qh = g_ph + ((size_t)b * NN + q0 + 16 * w) * DM + h * DHD;
    const __nv_bfloat16* Ql = g_pl + ((size_t)b * NN + q0 + 16 * w) * DM + h * DHD;
    const __nv_bfloat16* srcb[4] = {
        g_ph + ((size_t)(BB + b) * NN) * DM + h * DHD,        // K hi
        g_pl + ((size_t)(BB + b) * NN) * DM + h * DHD,        // K lo
        g_ph + ((size_t)(2 * BB + b) * NN) * DM + h * DHD,    // V hi
        g_pl + ((size_t)(2 * BB + b) * NN) * DM + h * DHD     // V lo
    };
    const unsigned* abr0 = g_adjb + ((size_t)b * NN + q0 + 16 * w + r) * (NN / 32);
    const unsigned* abr1 = abr0 + 8 * (NN / 32);

    const unsigned sb = (unsigned)__cvta_generic_to_shared(skv);

    // --- Q fragments (pre-scaled, pre-split) ---
    unsigned qh[2][4], ql[2][4];
    #pragma unroll
    for (int kc = 0; kc < 2; ++kc)
        #pragma unroll
        for (int i = 0; i < 4; ++i) {
            int ro = (i & 1) * 8;
            int co = (i >> 1) * 8;
            qh[kc][i] = *(const unsigned*)(Qh + (size_t)(r + ro) * DM + kc * 16 + co + c2);
            ql[kc][i] = *(const unsigned*)(Ql + (size_t)(r + ro) * DM + kc * 16 + co + c2);
        }

    float dacc[4][4];
    #pragma unroll
    for (int i = 0; i < 4; ++i)
        #pragma unroll
        for (int j = 0; j < 4; ++j) dacc[i][j] = 0.0f;
    float lsum0 = 0.0f, lsum1 = 0.0f;

    auto issue_tile = [&](int tt) {
        const int stage = tt & 1;
        const int m0 = tt * 128;
        const unsigned dstbase = sb + stage * STAGE_B;
        #pragma unroll
        for (int i = 0; i < 8; ++i) {
            int idx = t + i * 256;
            int buf = idx >> 9;
            int rem = idx & 511;
            int row = rem >> 2;
            int ch  = rem & 3;
            const __nv_bfloat16* src = srcb[buf] + (size_t)(m0 + row) * DM + ch * 8;
            cp_async16(dstbase + buf * BUF_B + row * (KS * 2) + ch * 16, src);
        }
    };

    issue_tile(0);
    asm volatile("cp.async.commit_group;\n");

    const int hstag = w & 1;   // warp-level half stagger

    for (int tt = 0; tt < NN / 128; ++tt) {
        const int m0 = tt * 128;
        if (tt + 1 < NN / 128) {
            issue_tile(tt + 1);
            asm volatile("cp.async.commit_group;\n");
            asm volatile("cp.async.wait_group 1;\n");
        } else {
            asm volatile("cp.async.wait_group 0;\n");
        }
        __syncthreads();

        const unsigned st  = sb + (tt & 1) * STAGE_B;
        const unsigned KHI = st;
        const unsigned KLO = st + BUF_B;
        const unsigned VHI = st + 2 * BUF_B;
        const unsigned VLO = st + 3 * BUF_B;

        #pragma unroll
        for (int hh = 0; hh < 2; ++hh) {
            const int half = hh ^ hstag;
            uint2 m0v = *(const uint2*)(abr0 + (m0 >> 5) + 2 * half);
            uint2 m1v = *(const uint2*)(abr1 + (m0 >> 5) + 2 * half);
            unsigned mw0[2] = {m0v.x, m0v.y};
            unsigned mw1[2] = {m1v.x, m1v.y};

            unsigned pah[4][4], pal[4][4];

            // np in pairs: 4 independent s accumulators, distance-4 chains
            #pragma unroll
            for (int nnp = 0; nnp < 2; ++nnp) {
                const int npA = half * 4 + 2 * nnp;
                const int npB = npA + 1;
                float sA0[4] = {0.f, 0.f, 0.f, 0.f};
                float sA1[4] = {0.f, 0.f, 0.f, 0.f};
                float sB0[4] = {0.f, 0.f, 0.f, 0.f};
                float sB1[4] = {0.f, 0.f, 0.f, 0.f};

                #pragma unroll
                for (int kc = 0; kc < 2; ++kc) {
                    const int rbase = (lane & 7) + ((lane & 16) ? 8 : 0);
                    const int col   = kc * 16 + ((lane & 8) ? 8 : 0);
                    unsigned kAh[4], kAl[4], kBh[4], kBl[4];
                    ldsm4(kAh[0], kAh[1], kAh[2], kAh[3], KHI + ((npA * 16 + rbase) * KS + col) * 2);
                    ldsm4(kAl[0], kAl[1], kAl[2], kAl[3], KLO + ((npA * 16 + rbase) * KS + col) * 2);
                    ldsm4(kBh[0], kBh[1], kBh[2], kBh[3], KHI + ((npB * 16 + rbase) * KS + col) * 2);
                    ldsm4(kBl[0], kBl[1], kBl[2], kBl[3], KLO + ((npB * 16 + rbase) * KS + col) * 2);
                    // term hh
                    mma16816(sA0, qh[kc], kAh[0], kAh[1]);
                    mma16816(sA1, qh[kc], kAh[2], kAh[3]);
                    mma16816(sB0, qh[kc], kBh[0], kBh[1]);
                    mma16816(sB1, qh[kc], kBh[2], kBh[3]);
                    // term lh
                    mma16816(sA0, ql[kc], kAh[0], kAh[1]);
                    mma16816(sA1, ql[kc], kAh[2], kAh[3]);
                    mma16816(sB0, ql[kc], kBh[0], kBh[1]);
                    mma16816(sB1, ql[kc], kBh[2], kBh[3]);
                    // term hl
                    mma16816(sA0, qh[kc], kAl[0], kAl[1]);
                    mma16816(sA1, qh[kc], kAl[2], kAl[3]);
                    mma16816(sB0, qh[kc], kBl[0], kBl[1]);
                    mma16816(sB1, qh[kc], kBl[2], kBl[3]);
                }

                // mask + 2^s + pack for npA then npB
                #pragma unroll
                for (int e = 0; e < 2; ++e) {
                    const int nn = 2 * nnp + e;
                    const int np = half * 4 + nn;
                    float* s0 = e ? sB0 : sA0;
                    float* s1 = e ? sB1 : sA1;
                    const unsigned w0 = mw0[nn >> 1], w1 = mw1[nn >> 1];
                    const int bit0 = (np & 1) * 16 + c2;
                    {
                        float p00 = ((w0 >> bit0) & 1)       ? ex2(s0[0]) : 0.0f;
                        float p01 = ((w0 >> (bit0 + 1)) & 1) ? ex2(s0[1]) : 0.0f;
                        float p10 = ((w1 >> bit0) & 1)       ? ex2(s0[2]) : 0.0f;
                        float p11 = ((w1 >> (bit0 + 1)) & 1) ? ex2(s0[3]) : 0.0f;
                        lsum0 += p00 + p01;
                        lsum1 += p10 + p11;
                        split2(p00, p01, pah[nn][0], pal[nn][0]);
                        split2(p10, p11, pah[nn][1], pal[nn][1]);
                    }
                    {
                        const int bit1 = bit0 + 8;
                        float p00 = ((w0 >> bit1) & 1)       ? ex2(s1[0]) : 0.0f;
                        float p01 = ((w0 >> (bit1 + 1)) & 1) ? ex2(s1[1]) : 0.0f;
                        float p10 = ((w1 >> bit1) & 1)       ? ex2(s1[2]) : 0.0f;
                        float p11 = ((w1 >> (bit1 + 1)) & 1) ? ex2(s1[3]) : 0.0f;
                        lsum0 += p00 + p01;
                        lsum1 += p10 + p11;
                        split2(p00, p01, pah[nn][2], pal[nn][2]);
                        split2(p10, p11, pah[nn][3], pal[nn][3]);
                    }
                }
            }

            // --- dacc += P(half) @ V(half rows): preload 16 V regs, distance-4 ---
            #pragma unroll
            for (int kt = 0; kt < 4; ++kt) {
                const int row  = (half * 4 + kt) * 16 + (lane & 7) + ((lane & 8) ? 8 : 0);
                const int colA = (lane & 16) ? 8 : 0;
                unsigned avh[4], avl[4], bvh[4], bvl[4];
                ldsm4t(avh[0], avh[1], avh[2], avh[3], VHI + (row * KS + colA) * 2);
                ldsm4t(avl[0], avl[1], avl[2], avl[3], VLO + (row * KS + colA) * 2);
                ldsm4t(bvh[0], bvh[1], bvh[2], bvh[3], VHI + (row * KS + colA + 16) * 2);
                ldsm4t(bvl[0], bvl[1], bvl[2], bvl[3], VLO + (row * KS + colA + 16) * 2);
                // term ph * vh
                mma16816(dacc[0], pah[kt], avh[0], avh[1]);
                mma16816(dacc[1], pah[kt], avh[2], avh[3]);
                mma16816(dacc[2], pah[kt], bvh[0], bvh[1]);
                mma16816(dacc[3], pah[kt], bvh[2], bvh[3]);
                // term pl * vh
                mma16816(dacc[0], pal[kt], avh[0], avh[1]);
                mma16816(dacc[1], pal[kt], avh[2], avh[3]);
                mma16816(dacc[2], pal[kt], bvh[0], bvh[1]);
                mma16816(dacc[3], pal[kt], bvh[2], bvh[3]);
                // term ph * vl
                mma16816(dacc[0], pah[kt], avl[0], avl[1]);
                mma16816(dacc[1], pah[kt], avl[2], avl[3]);
                mma16816(dacc[2], pah[kt], bvl[0], bvl[1]);
                mma16816(dacc[3], pah[kt], bvl[2], bvl[3]);
            }
        }
        __syncthreads();
    }

    // --- row-sum reduce (lanes xor 1,2 share a row) + split write ---
    lsum0 += __shfl_xor_sync(0xffffffffu, lsum0, 1);
    lsum0 += __shfl_xor_sync(0xffffffffu, lsum0, 2);
    lsum1 += __shfl_xor_sync(0xffffffffu, lsum1, 1);
    lsum1 += __shfl_xor_sync(0xffffffffu, lsum1, 2);
    float inv0 = 1.0f / lsum0;
    float inv1 = 1.0f / lsum1;

    __nv_bfloat16* ogh = g_ah + ((size_t)b * NN + q0 + 16 * w) * DM + h * DHD;
    __nv_bfloat16* ogl = g_al + ((size_t)b * NN + q0 + 16 * w) * DM + h * DHD;
    #pragma unroll
    for (int nd = 0; nd < 4; ++nd) {
        unsigned h0, l0, h1, l1;
        split2(dacc[nd][0] * inv0, dacc[nd][1] * inv0, h0, l0);
        split2(dacc[nd][2] * inv1, dacc[nd][3] * inv1, h1, l1);
        *(unsigned*)(ogh + (size_t)r * DM + nd * 8 + c2)       = h0;
        *(unsigned*)(ogl + (size_t)r * DM + nd * 8 + c2)       = l0;
        *(unsigned*)(ogh + (size_t)(r + 8) * DM + nd * 8 + c2) = h1;
        *(unsigned*)(ogl + (size_t)(r + 8) * DM + nd * 8 + c2) = l1;
    }
}

// ---------------------------------------------------------------------------
// Launch
// ---------------------------------------------------------------------------
extern "C" void kernel_launch(void* const* d_in, const int* in_sizes, int n_in,
                              void* d_out, int out_size)
{
    const float* x   = (const float*)d_in[0];
    const float* adj = (const float*)d_in[1];
    const float* Wq  = (const float*)d_in[2];
    const float* Wk  = (const float*)d_in[3];
    const float* Wv  = (const float*)d_in[4];
    const float* Wo  = (const float*)d_in[5];
    const float* bo  = (const float*)d_in[6];
    float* out = (float*)d_out;

    __nv_bfloat16 *xh, *xl, *wh, *wl, *ph, *pl, *ah, *al;
    cudaGetSymbolAddress((void**)&xh, g_xh);
    cudaGetSymbolAddress((void**)&xl, g_xl);
    cudaGetSymbolAddress((void**)&wh, g_wh);
    cudaGetSymbolAddress((void**)&wl, g_wl);
    cudaGetSymbolAddress((void**)&ph, g_ph);
    cudaGetSymbolAddress((void**)&pl, g_pl);
    cudaGetSymbolAddress((void**)&ah, g_ah);
    cudaGetSymbolAddress((void**)&al, g_al);

    const int gemm_smem = 2 * GSTAGE_B;   // 73728
    const int attn_smem = 2 * STAGE_B;    // 81920
    cudaFuncSetAttribute(gemm_split, cudaFuncAttributeMaxDynamicSharedMemorySize, gemm_smem);
    cudaFuncSetAttribute(attn_mma,   cudaFuncAttributeMaxDynamicSharedMemorySize, attn_smem);

    // prep: x split (1024 blocks) + W split (256 blocks)
    prep_kernel<<<1280, 256>>>(x, Wq, Wk, Wv, Wo);

    // QKV projections (z=0..2) + adjacency bitmask (z=3, concurrent);
    // Q pre-scaled by (1/sqrt(dh)) * log2(e) so attn uses 2^s
    gemm_split<<<dim3(64, 4, 4), 256, gemm_smem>>>(
        xh, xl, wh, wl, ph, pl, nullptr, nullptr,
        0.17677669529663687f * 1.4426950408889634f, adj);

    // attention
    attn_mma<<<dim3(NN / 128, HH, BB), 256, attn_smem>>>(0);

    // output projection: A @ Wo^T + bo
    gemm_split<<<dim3(64, 4, 1), 256, gemm_smem>>>(
        ah, al, wh + 3 * DM * DM, wl + 3 * DM * DM,
        nullptr, nullptr, out, bo, 1.0f, nullptr);
}